// round 10
// baseline (speedup 1.0000x reference)
#include <cuda_runtime.h>
#include <stdint.h>

#define CC   128
#define CI   32
#define HH   128
#define WW   256
#define BB   8
#define HW   (HH*WW)

// Precomputed parameters (filled by prep kernel each launch; deterministic).
__device__ uint32_t g_w1m[CI][4];
__device__ float    g_inv1[CI], g_bb1[CI];
__device__ uint32_t g_w2m[CI][9];
__device__ float    g_inv2[CI], g_bb2[CI];
__device__ uint32_t g_w3m[CC];
__device__ float    g_inv3[CC], g_bb3[CC];

// Scratch: binarized activations, 32 channels packed per pixel. 1 MB each.
__device__ uint32_t g_h1b[BB * HW];
__device__ uint32_t g_h2b[BB * HW];

// ---------------------------------------------------------------------------
// Prep: ONE mask word per warp (544 words over 68 blocks x 8 warps).
// bit c = (w > 0);  bn(z) = z*inv + bb, inv = g/sqrt(v+eps) > 0, bb = b - m*inv
// ---------------------------------------------------------------------------
__global__ void __launch_bounds__(256) prep_kernel(
    const float* __restrict__ w1, const float* __restrict__ g1,
    const float* __restrict__ b1, const float* __restrict__ m1, const float* __restrict__ v1,
    const float* __restrict__ w2, const float* __restrict__ g2,
    const float* __restrict__ b2, const float* __restrict__ m2, const float* __restrict__ v2,
    const float* __restrict__ w3, const float* __restrict__ g3,
    const float* __restrict__ b3, const float* __restrict__ m3, const float* __restrict__ v3)
{
    int tid  = threadIdx.x;
    int lane = tid & 31;
    int gw   = blockIdx.x * 8 + (tid >> 5);   // global word id 0..543

    if (gw < 128) {
        int oc = gw >> 2, j = gw & 3;
        uint32_t m = __ballot_sync(0xffffffffu, w1[oc * CC + j * 32 + lane] > 0.f);
        if (lane == 0) g_w1m[oc][j] = m;
    } else if (gw < 416) {
        int idx = gw - 128;
        int oc = idx / 9, t9 = idx - oc * 9;
        uint32_t m = __ballot_sync(0xffffffffu, w2[oc * (CI * 9) + lane * 9 + t9] > 0.f);
        if (lane == 0) g_w2m[oc][t9] = m;
    } else if (gw < 544) {
        int c = gw - 416;
        uint32_t m = __ballot_sync(0xffffffffu, w3[c * CI + lane] > 0.f);
        if (lane == 0) g_w3m[c] = m;
    }

    if (blockIdx.x == 0) {
        if (tid < CI) {
            float inv = __fdiv_rn(g1[tid], __fsqrt_rn(__fadd_rn(v1[tid], 1e-5f)));
            g_inv1[tid] = inv;
            g_bb1[tid]  = __fadd_rn(b1[tid], -__fmul_rn(m1[tid], inv));
        } else if (tid >= 64 && tid < 64 + CI) {
            int t = tid - 64;
            float inv = __fdiv_rn(g2[t], __fsqrt_rn(__fadd_rn(v2[t], 1e-5f)));
            g_inv2[t] = inv;
            g_bb2[t]  = __fadd_rn(b2[t], -__fmul_rn(m2[t], inv));
        } else if (tid >= 128) {
            int t = tid - 128;
            float inv = __fdiv_rn(g3[t], __fsqrt_rn(__fadd_rn(v3[t], 1e-5f)));
            g_inv3[t] = inv;
            g_bb3[t]  = __fadd_rn(b3[t], -__fmul_rn(m3[t], inv));
        }
    }
}

// ---------------------------------------------------------------------------
// Kernel A: conv1 (1x1, 128->32) + bn + sign -> packed h1 bitmask per pixel.
// Pure streaming, 1 px/thread, 1024 blocks (measured ~6.1 TB/s).
// ---------------------------------------------------------------------------
__global__ void __launch_bounds__(256) k_conv1(const float* __restrict__ x)
{
    __shared__ uint32_t sw1[CI][4];
    __shared__ float sinv1[CI], sbb1[CI];
    int tid = threadIdx.x;
    if (tid < CI) {
        sinv1[tid] = g_inv1[tid]; sbb1[tid] = g_bb1[tid];
        #pragma unroll
        for (int j = 0; j < 4; j++) sw1[tid][j] = g_w1m[tid][j];
    }
    __syncthreads();

    int px = blockIdx.x * 256 + tid;     // 0 .. B*H*W-1 (exact multiple)
    int b  = px / HW;
    int p  = px - b * HW;
    const float* xp = x + (size_t)b * (CC * HW) + p;

    uint32_t s0 = 0, s1 = 0, s2 = 0, s3 = 0;
    #pragma unroll
    for (int i = 0; i < 32; i++) {
        if (xp[(i      ) * HW] > 0.f) s0 |= (1u << i);
        if (xp[(i +  32) * HW] > 0.f) s1 |= (1u << i);
        if (xp[(i +  64) * HW] > 0.f) s2 |= (1u << i);
        if (xp[(i +  96) * HW] > 0.f) s3 |= (1u << i);
    }

    uint32_t outm = 0;
    #pragma unroll
    for (int oc = 0; oc < CI; oc++) {
        int pc = __popc(s0 ^ sw1[oc][0]) + __popc(s1 ^ sw1[oc][1])
               + __popc(s2 ^ sw1[oc][2]) + __popc(s3 ^ sw1[oc][3]);
        float z = (float)(128 - 2 * pc);
        float v = __fadd_rn(__fmul_rn(z, sinv1[oc]), sbb1[oc]);
        if (v > 0.f) outm |= (1u << oc);
    }
    g_h1b[px] = outm;
}

// ---------------------------------------------------------------------------
// Kernel B: conv2 (3x3, zero-pad AFTER binarize) + bn + sign -> h2 bitmask.
// Mask -> mask only (1 MB in / 1 MB out, L2-resident). Tile 32x8, smem halo.
// ---------------------------------------------------------------------------
#define TW 32
#define TH 8

__global__ void __launch_bounds__(256) k_conv2()
{
    __shared__ uint32_t sh1[TH + 2][TW + 2];
    __shared__ uint32_t sw2[CI][9];
    __shared__ float sinv2[CI], sbb2[CI];

    int tid = threadIdx.x;
    int tx = tid & (TW - 1);
    int ty = tid / TW;
    int w0 = blockIdx.x * TW;
    int h0 = blockIdx.y * TH;
    int b  = blockIdx.z;

    if (tid < CI) {
        sinv2[tid] = g_inv2[tid]; sbb2[tid] = g_bb2[tid];
        #pragma unroll
        for (int t9 = 0; t9 < 9; t9++) sw2[tid][t9] = g_w2m[tid][t9];
    }

    const bool border = (w0 == 0) | (h0 == 0) | (w0 + TW == WW) | (h0 + TH == HH);

    // Load h1 bitmask tile + 1-pixel halo
    const uint32_t* h1b = g_h1b + (size_t)b * HW;
    for (int it = tid; it < (TH + 2) * (TW + 2); it += 256) {
        int hy = it / (TW + 2), hx = it - hy * (TW + 2);
        int gh = h0 + hy - 1, gw = w0 + hx - 1;
        uint32_t v = 0;
        if (gh >= 0 && gh < HH && gw >= 0 && gw < WW) v = h1b[gh * WW + gw];
        sh1[hy][hx] = v;
    }
    __syncthreads();

    int gh = h0 + ty, gw = w0 + tx;

    // Center of (ty,tx) at sh1[ty+1][tx+1]; tap t offset (t/3-1, t%3-1)
    // -> gather sh1[ty + t/3][tx + t%3].
    uint32_t n[9];
    #pragma unroll
    for (int t = 0; t < 9; t++)
        n[t] = sh1[ty + t / 3][tx + t % 3];

    uint32_t h2b = 0;
    if (!border) {
        #pragma unroll
        for (int oc = 0; oc < CI; oc++) {
            int pc = 0;
            #pragma unroll
            for (int t = 0; t < 9; t++) pc += __popc(n[t] ^ sw2[oc][t]);
            float v = __fadd_rn(__fmul_rn((float)(288 - 2 * pc), sinv2[oc]), sbb2[oc]);
            if (v > 0.f) h2b |= (1u << oc);
        }
    } else {
        bool ok[9];
        #pragma unroll
        for (int t = 0; t < 9; t++) {
            int yy = gh + t / 3 - 1, xx = gw + t % 3 - 1;
            ok[t] = (yy >= 0) & (yy < HH) & (xx >= 0) & (xx < WW);
        }
        #pragma unroll
        for (int oc = 0; oc < CI; oc++) {
            int z = 0;
            #pragma unroll
            for (int t = 0; t < 9; t++) {
                int c9 = 32 - 2 * __popc(n[t] ^ sw2[oc][t]);
                z += ok[t] ? c9 : 0;
            }
            float v = __fadd_rn(__fmul_rn((float)z, sinv2[oc]), sbb2[oc]);
            if (v > 0.f) h2b |= (1u << oc);
        }
    }

    g_h2b[(size_t)b * HW + (size_t)gh * WW + gw] = h2b;
}

// ---------------------------------------------------------------------------
// Kernel C: conv3 (1x1, 32->128) + bn + prelu + residual + prelu.
// PURE STREAMING: no barriers, no smem tile. h2b word per pixel (L2 hit),
// coalesced x reads, __stwt out writes.
// ---------------------------------------------------------------------------
__global__ void __launch_bounds__(256) k_conv3s(
    const float* __restrict__ x, float* __restrict__ out,
    const float* __restrict__ a3p, const float* __restrict__ aoutp)
{
    __shared__ uint32_t sw3[CC];
    __shared__ float sinv3[CC], sbb3[CC];

    int tid = threadIdx.x;
    if (tid < CC) { sw3[tid] = g_w3m[tid]; sinv3[tid] = g_inv3[tid]; sbb3[tid] = g_bb3[tid]; }
    __syncthreads();

    int px = blockIdx.x * 256 + tid;     // 0 .. B*H*W-1
    int b  = px / HW;
    int p  = px - b * HW;

    uint32_t h2b = g_h2b[px];
    float a3   = a3p[0];
    float aout = aoutp[0];

    size_t base = (size_t)b * (CC * HW) + p;
    const float* xp = x + base;
    float* op = out + base;

    #pragma unroll 16
    for (int c = 0; c < CC; c++) {
        int z = 32 - 2 * __popc(h2b ^ sw3[c]);
        float v = __fadd_rn(__fmul_rn((float)z, sinv3[c]), sbb3[c]);
        v = (v >= 0.f) ? v : a3 * v;
        float s = v + xp[(size_t)c * HW];
        s = (s >= 0.f) ? s : aout * s;
        __stwt(op + (size_t)c * HW, s);
    }
}

// ---------------------------------------------------------------------------
extern "C" void kernel_launch(void* const* d_in, const int* in_sizes, int n_in,
                              void* d_out, int out_size)
{
    const float* x  = (const float*)d_in[0];
    const float* w1 = (const float*)d_in[1];
    const float* g1 = (const float*)d_in[2];
    const float* b1 = (const float*)d_in[3];
    const float* m1 = (const float*)d_in[4];
    const float* v1 = (const float*)d_in[5];
    // d_in[6] = a1 (unused: prelu with a>0 never changes the following sign)
    const float* w2 = (const float*)d_in[7];
    const float* g2 = (const float*)d_in[8];
    const float* b2 = (const float*)d_in[9];
    const float* m2 = (const float*)d_in[10];
    const float* v2 = (const float*)d_in[11];
    // d_in[12] = a2 (unused, same reason)
    const float* w3 = (const float*)d_in[13];
    const float* g3 = (const float*)d_in[14];
    const float* b3 = (const float*)d_in[15];
    const float* m3 = (const float*)d_in[16];
    const float* v3 = (const float*)d_in[17];
    const float* a3 = (const float*)d_in[18];
    const float* ao = (const float*)d_in[19];
    float* out = (float*)d_out;

    prep_kernel<<<68, 256>>>(w1, g1, b1, m1, v1,
                             w2, g2, b2, m2, v2,
                             w3, g3, b3, m3, v3);

    k_conv1<<<(BB * HW) / 256, 256>>>(x);

    dim3 grid2(WW / TW, HH / TH, BB);   // 8 x 16 x 8 = 1024 blocks
    k_conv2<<<grid2, 256>>>();

    k_conv3s<<<(BB * HW) / 256, 256>>>(x, out, a3, ao);
}

// round 12
// speedup vs baseline: 1.0638x; 1.0638x over previous
#include <cuda_runtime.h>
#include <stdint.h>

#define CC   128
#define CI   32
#define HH   128
#define WW   256
#define BB   8
#define HW   (HH*WW)

// Precomputed parameters (filled by prep kernel each launch; deterministic).
__device__ uint32_t g_w1m[CI][4];
__device__ float    g_inv1[CI], g_bb1[CI];
__device__ uint32_t g_w2m[CI][9];
__device__ float    g_inv2[CI], g_bb2[CI];
__device__ uint32_t g_w3m[CC];
__device__ float    g_inv3[CC], g_bb3[CC];

// Scratch: h1 binarized activations, 32 channels packed per pixel. 1 MB.
__device__ uint32_t g_h1b[BB * HW];

// ---------------------------------------------------------------------------
// Prep: ONE mask word per warp (544 words over 68 blocks x 8 warps).
// bit c = (w > 0);  bn(z) = z*inv + bb, inv = g/sqrt(v+eps) > 0, bb = b - m*inv
// ---------------------------------------------------------------------------
__global__ void __launch_bounds__(256) prep_kernel(
    const float* __restrict__ w1, const float* __restrict__ g1,
    const float* __restrict__ b1, const float* __restrict__ m1, const float* __restrict__ v1,
    const float* __restrict__ w2, const float* __restrict__ g2,
    const float* __restrict__ b2, const float* __restrict__ m2, const float* __restrict__ v2,
    const float* __restrict__ w3, const float* __restrict__ g3,
    const float* __restrict__ b3, const float* __restrict__ m3, const float* __restrict__ v3)
{
    int tid  = threadIdx.x;
    int lane = tid & 31;
    int gw   = blockIdx.x * 8 + (tid >> 5);   // global word id 0..543

    if (gw < 128) {
        int oc = gw >> 2, j = gw & 3;
        uint32_t m = __ballot_sync(0xffffffffu, w1[oc * CC + j * 32 + lane] > 0.f);
        if (lane == 0) g_w1m[oc][j] = m;
    } else if (gw < 416) {
        int idx = gw - 128;
        int oc = idx / 9, t9 = idx - oc * 9;
        uint32_t m = __ballot_sync(0xffffffffu, w2[oc * (CI * 9) + lane * 9 + t9] > 0.f);
        if (lane == 0) g_w2m[oc][t9] = m;
    } else if (gw < 544) {
        int c = gw - 416;
        uint32_t m = __ballot_sync(0xffffffffu, w3[c * CI + lane] > 0.f);
        if (lane == 0) g_w3m[c] = m;
    }

    if (blockIdx.x == 0) {
        if (tid < CI) {
            float inv = __fdiv_rn(g1[tid], __fsqrt_rn(__fadd_rn(v1[tid], 1e-5f)));
            g_inv1[tid] = inv;
            g_bb1[tid]  = __fadd_rn(b1[tid], -__fmul_rn(m1[tid], inv));
        } else if (tid >= 64 && tid < 64 + CI) {
            int t = tid - 64;
            float inv = __fdiv_rn(g2[t], __fsqrt_rn(__fadd_rn(v2[t], 1e-5f)));
            g_inv2[t] = inv;
            g_bb2[t]  = __fadd_rn(b2[t], -__fmul_rn(m2[t], inv));
        } else if (tid >= 128) {
            int t = tid - 128;
            float inv = __fdiv_rn(g3[t], __fsqrt_rn(__fadd_rn(v3[t], 1e-5f)));
            g_inv3[t] = inv;
            g_bb3[t]  = __fadd_rn(b3[t], -__fmul_rn(m3[t], inv));
        }
    }
}

// ---------------------------------------------------------------------------
// Kernel A: conv1 (1x1, 128->32) + bn + sign -> packed h1 bitmask per pixel.
// Pure streaming, 1 px/thread, 1024 blocks (measured ~6.1 TB/s).
// ---------------------------------------------------------------------------
__global__ void __launch_bounds__(256) k_conv1(const float* __restrict__ x)
{
    __shared__ uint32_t sw1[CI][4];
    __shared__ float sinv1[CI], sbb1[CI];
    int tid = threadIdx.x;
    if (tid < CI) {
        sinv1[tid] = g_inv1[tid]; sbb1[tid] = g_bb1[tid];
        #pragma unroll
        for (int j = 0; j < 4; j++) sw1[tid][j] = g_w1m[tid][j];
    }
    __syncthreads();

    int px = blockIdx.x * 256 + tid;     // 0 .. B*H*W-1 (exact multiple)
    int b  = px / HW;
    int p  = px - b * HW;
    const float* xp = x + (size_t)b * (CC * HW) + p;

    uint32_t s0 = 0, s1 = 0, s2 = 0, s3 = 0;
    #pragma unroll
    for (int i = 0; i < 32; i++) {
        if (xp[(i      ) * HW] > 0.f) s0 |= (1u << i);
        if (xp[(i +  32) * HW] > 0.f) s1 |= (1u << i);
        if (xp[(i +  64) * HW] > 0.f) s2 |= (1u << i);
        if (xp[(i +  96) * HW] > 0.f) s3 |= (1u << i);
    }

    uint32_t outm = 0;
    #pragma unroll
    for (int oc = 0; oc < CI; oc++) {
        int pc = __popc(s0 ^ sw1[oc][0]) + __popc(s1 ^ sw1[oc][1])
               + __popc(s2 ^ sw1[oc][2]) + __popc(s3 ^ sw1[oc][3]);
        float z = (float)(128 - 2 * pc);
        float v = __fadd_rn(__fmul_rn(z, sinv1[oc]), sbb1[oc]);
        if (v > 0.f) outm |= (1u << oc);
    }
    g_h1b[px] = outm;
}

// ---------------------------------------------------------------------------
// Kernel B (row kernel): one block = one image row (256 px, 256 threads).
//  phase 1: load h1 rows h-1,h,h+1 (+col halo) into smem (L2 hits).
//  phase 2: conv2+bn+sign, 1 px/thread -> sh2[256].
//  phase 3: conv3+bn+prelu+residual+prelu, VECTORIZED: each thread owns
//           4 pixels x 32 channels -> 32x (LDG.128 + STG.128) instead of
//           128x scalar pairs (kills the STG.32 issue bottleneck measured
//           in R10: 5 cyc/STG.32 -> 12 cyc/STG.128 per 16B).
// Grid: BB*HH = 1024 blocks.
// ---------------------------------------------------------------------------
__global__ void __launch_bounds__(256) k_row(
    const float* __restrict__ x, float* __restrict__ out,
    const float* __restrict__ a3p, const float* __restrict__ aoutp)
{
    // sh2 MUST be 16B-aligned: it is read via uint4 in phase 3.
    // (R11 bug: sh1=774 words put sh2 at offset 8 mod 16 -> LDS.128 trap.)
    __shared__ __align__(16) uint32_t sh2[WW];
    __shared__ __align__(16) uint32_t sh1[3][WW + 2]; // col +1 shift; ends zero
    __shared__ uint32_t sw2[CI][9];
    __shared__ float sinv2[CI], sbb2[CI];
    __shared__ uint32_t sw3[CC];
    __shared__ float sinv3[CC], sbb3[CC];

    int tid = threadIdx.x;
    int row = blockIdx.x & (HH - 1);
    int b   = blockIdx.x >> 7;

    if (tid < CC) { sw3[tid] = g_w3m[tid]; sinv3[tid] = g_inv3[tid]; sbb3[tid] = g_bb3[tid]; }
    if (tid < CI) {
        sinv2[tid] = g_inv2[tid]; sbb2[tid] = g_bb2[tid];
        #pragma unroll
        for (int t9 = 0; t9 < 9; t9++) sw2[tid][t9] = g_w2m[tid][t9];
    }

    // ---- Phase 1: h1 rows (from L2-resident g_h1b) ----
    const uint32_t* h1 = g_h1b + (size_t)b * HW;
    #pragma unroll
    for (int r = 0; r < 3; r++) {
        int y = row - 1 + r;
        sh1[r][tid + 1] = (y >= 0 && y < HH) ? h1[y * WW + tid] : 0u;
    }
    if (tid < 3) { sh1[tid][0] = 0u; sh1[tid][WW + 1] = 0u; }
    __syncthreads();

    // ---- Phase 2: conv2+bn+sign for pixel w = tid ----
    {
        uint32_t n[9];
        #pragma unroll
        for (int t = 0; t < 9; t++)
            n[t] = sh1[t / 3][tid + t % 3];   // col tid-1+(t%3), +1 shift

        uint32_t h2b = 0;
        const bool interior = (row > 0) & (row < HH - 1) & (tid > 0) & (tid < WW - 1);
        if (interior) {
            #pragma unroll
            for (int oc = 0; oc < CI; oc++) {
                int pc = 0;
                #pragma unroll
                for (int t = 0; t < 9; t++) pc += __popc(n[t] ^ sw2[oc][t]);
                float v = __fadd_rn(__fmul_rn((float)(288 - 2 * pc), sinv2[oc]), sbb2[oc]);
                if (v > 0.f) h2b |= (1u << oc);
            }
        } else {
            bool ok[9];
            #pragma unroll
            for (int t = 0; t < 9; t++) {
                int yy = row + t / 3 - 1, xx = tid + t % 3 - 1;
                ok[t] = (yy >= 0) & (yy < HH) & (xx >= 0) & (xx < WW);
            }
            #pragma unroll
            for (int oc = 0; oc < CI; oc++) {
                int z = 0;
                #pragma unroll
                for (int t = 0; t < 9; t++) {
                    int c9 = 32 - 2 * __popc(n[t] ^ sw2[oc][t]);
                    z += ok[t] ? c9 : 0;
                }
                float v = __fadd_rn(__fmul_rn((float)z, sinv2[oc]), sbb2[oc]);
                if (v > 0.f) h2b |= (1u << oc);
            }
        }
        sh2[tid] = h2b;
    }
    __syncthreads();

    // ---- Phase 3: conv3 + residual, 4 px x 32 ch per thread, float4 I/O ----
    int px0 = (tid >> 2) << 2;          // 4-aligned pixel group in row
    int cq  = (tid & 3) * 32;           // channel quarter

    uint4 h2v = *(const uint4*)&sh2[px0];
    uint32_t h2[4] = { h2v.x, h2v.y, h2v.z, h2v.w };

    float a3   = a3p[0];
    float aout = aoutp[0];
    size_t base = (size_t)b * (CC * HW) + (size_t)row * WW + px0;
    const float* xp = x + base;
    float* op = out + base;

    #pragma unroll 8
    for (int c = 0; c < 32; c++) {
        int ch = cq + c;
        uint32_t wc = sw3[ch];
        float inv = sinv3[ch], bb = sbb3[ch];
        float v0 = __fadd_rn(__fmul_rn((float)(32 - 2 * __popc(h2[0] ^ wc)), inv), bb);
        float v1 = __fadd_rn(__fmul_rn((float)(32 - 2 * __popc(h2[1] ^ wc)), inv), bb);
        float v2 = __fadd_rn(__fmul_rn((float)(32 - 2 * __popc(h2[2] ^ wc)), inv), bb);
        float v3 = __fadd_rn(__fmul_rn((float)(32 - 2 * __popc(h2[3] ^ wc)), inv), bb);
        v0 = (v0 >= 0.f) ? v0 : a3 * v0;
        v1 = (v1 >= 0.f) ? v1 : a3 * v1;
        v2 = (v2 >= 0.f) ? v2 : a3 * v2;
        v3 = (v3 >= 0.f) ? v3 : a3 * v3;
        float4 xv = *(const float4*)(xp + (size_t)ch * HW);
        float s0 = v0 + xv.x, s1 = v1 + xv.y, s2 = v2 + xv.z, s3 = v3 + xv.w;
        s0 = (s0 >= 0.f) ? s0 : aout * s0;
        s1 = (s1 >= 0.f) ? s1 : aout * s1;
        s2 = (s2 >= 0.f) ? s2 : aout * s2;
        s3 = (s3 >= 0.f) ? s3 : aout * s3;
        __stwt((float4*)(op + (size_t)ch * HW), make_float4(s0, s1, s2, s3));
    }
}

// ---------------------------------------------------------------------------
extern "C" void kernel_launch(void* const* d_in, const int* in_sizes, int n_in,
                              void* d_out, int out_size)
{
    const float* x  = (const float*)d_in[0];
    const float* w1 = (const float*)d_in[1];
    const float* g1 = (const float*)d_in[2];
    const float* b1 = (const float*)d_in[3];
    const float* m1 = (const float*)d_in[4];
    const float* v1 = (const float*)d_in[5];
    // d_in[6] = a1 (unused: prelu with a>0 never changes the following sign)
    const float* w2 = (const float*)d_in[7];
    const float* g2 = (const float*)d_in[8];
    const float* b2 = (const float*)d_in[9];
    const float* m2 = (const float*)d_in[10];
    const float* v2 = (const float*)d_in[11];
    // d_in[12] = a2 (unused, same reason)
    const float* w3 = (const float*)d_in[13];
    const float* g3 = (const float*)d_in[14];
    const float* b3 = (const float*)d_in[15];
    const float* m3 = (const float*)d_in[16];
    const float* v3 = (const float*)d_in[17];
    const float* a3 = (const float*)d_in[18];
    const float* ao = (const float*)d_in[19];
    float* out = (float*)d_out;

    prep_kernel<<<68, 256>>>(w1, g1, b1, m1, v1,
                             w2, g2, b2, m2, v2,
                             w3, g3, b3, m3, v3);

    k_conv1<<<(BB * HW) / 256, 256>>>(x);

    k_row<<<BB * HH, 256>>>(x, out, a3, ao);   // 1024 blocks, 1 row each
}

// round 13
// speedup vs baseline: 1.0785x; 1.0139x over previous
#include <cuda_runtime.h>
#include <stdint.h>

#define CC   128
#define CI   32
#define HH   128
#define WW   256
#define BB   8
#define HW   (HH*WW)

// Precomputed parameters (filled by prep kernel each launch; deterministic).
__device__ uint32_t g_w1m[CI][4];
__device__ float    g_inv1[CI], g_bb1[CI];
__device__ uint32_t g_w2m[CI][9];
__device__ float    g_inv2[CI], g_bb2[CI];
__device__ uint32_t g_w3m[CC];
__device__ float    g_inv3[CC], g_bb3[CC];

// Scratch: h1 binarized activations, 32 channels packed per pixel. 1 MB.
__device__ uint32_t g_h1b[BB * HW];

// ---------------------------------------------------------------------------
// Prep: ONE mask word per warp (544 words over 68 blocks x 8 warps).
// bit c = (w > 0);  bn(z) = z*inv + bb, inv = g/sqrt(v+eps) > 0, bb = b - m*inv
// ---------------------------------------------------------------------------
__global__ void __launch_bounds__(256) prep_kernel(
    const float* __restrict__ w1, const float* __restrict__ g1,
    const float* __restrict__ b1, const float* __restrict__ m1, const float* __restrict__ v1,
    const float* __restrict__ w2, const float* __restrict__ g2,
    const float* __restrict__ b2, const float* __restrict__ m2, const float* __restrict__ v2,
    const float* __restrict__ w3, const float* __restrict__ g3,
    const float* __restrict__ b3, const float* __restrict__ m3, const float* __restrict__ v3)
{
    int tid  = threadIdx.x;
    int lane = tid & 31;
    int gw   = blockIdx.x * 8 + (tid >> 5);   // global word id 0..543

    if (gw < 128) {
        int oc = gw >> 2, j = gw & 3;
        uint32_t m = __ballot_sync(0xffffffffu, w1[oc * CC + j * 32 + lane] > 0.f);
        if (lane == 0) g_w1m[oc][j] = m;
    } else if (gw < 416) {
        int idx = gw - 128;
        int oc = idx / 9, t9 = idx - oc * 9;
        uint32_t m = __ballot_sync(0xffffffffu, w2[oc * (CI * 9) + lane * 9 + t9] > 0.f);
        if (lane == 0) g_w2m[oc][t9] = m;
    } else if (gw < 544) {
        int c = gw - 416;
        uint32_t m = __ballot_sync(0xffffffffu, w3[c * CI + lane] > 0.f);
        if (lane == 0) g_w3m[c] = m;
    }

    if (blockIdx.x == 0) {
        if (tid < CI) {
            float inv = __fdiv_rn(g1[tid], __fsqrt_rn(__fadd_rn(v1[tid], 1e-5f)));
            g_inv1[tid] = inv;
            g_bb1[tid]  = __fadd_rn(b1[tid], -__fmul_rn(m1[tid], inv));
        } else if (tid >= 64 && tid < 64 + CI) {
            int t = tid - 64;
            float inv = __fdiv_rn(g2[t], __fsqrt_rn(__fadd_rn(v2[t], 1e-5f)));
            g_inv2[t] = inv;
            g_bb2[t]  = __fadd_rn(b2[t], -__fmul_rn(m2[t], inv));
        } else if (tid >= 128) {
            int t = tid - 128;
            float inv = __fdiv_rn(g3[t], __fsqrt_rn(__fadd_rn(v3[t], 1e-5f)));
            g_inv3[t] = inv;
            g_bb3[t]  = __fadd_rn(b3[t], -__fmul_rn(m3[t], inv));
        }
    }
}

// ---------------------------------------------------------------------------
// Kernel A: conv1 (1x1, 128->32) + bn + sign -> packed h1 bitmask per pixel.
// Pure streaming FORWARD order; on exit, L2 holds the LAST ~126MB of x.
// ---------------------------------------------------------------------------
__global__ void __launch_bounds__(256) k_conv1(const float* __restrict__ x)
{
    __shared__ uint32_t sw1[CI][4];
    __shared__ float sinv1[CI], sbb1[CI];
    int tid = threadIdx.x;
    if (tid < CI) {
        sinv1[tid] = g_inv1[tid]; sbb1[tid] = g_bb1[tid];
        #pragma unroll
        for (int j = 0; j < 4; j++) sw1[tid][j] = g_w1m[tid][j];
    }
    __syncthreads();

    int px = blockIdx.x * 256 + tid;     // 0 .. B*H*W-1 (exact multiple)
    int b  = px / HW;
    int p  = px - b * HW;
    const float* xp = x + (size_t)b * (CC * HW) + p;

    uint32_t s0 = 0, s1 = 0, s2 = 0, s3 = 0;
    #pragma unroll
    for (int i = 0; i < 32; i++) {
        if (xp[(i      ) * HW] > 0.f) s0 |= (1u << i);
        if (xp[(i +  32) * HW] > 0.f) s1 |= (1u << i);
        if (xp[(i +  64) * HW] > 0.f) s2 |= (1u << i);
        if (xp[(i +  96) * HW] > 0.f) s3 |= (1u << i);
    }

    uint32_t outm = 0;
    #pragma unroll
    for (int oc = 0; oc < CI; oc++) {
        int pc = __popc(s0 ^ sw1[oc][0]) + __popc(s1 ^ sw1[oc][1])
               + __popc(s2 ^ sw1[oc][2]) + __popc(s3 ^ sw1[oc][3]);
        float z = (float)(128 - 2 * pc);
        float v = __fadd_rn(__fmul_rn(z, sinv1[oc]), sbb1[oc]);
        if (v > 0.f) outm |= (1u << oc);
    }
    g_h1b[px] = outm;
}

// ---------------------------------------------------------------------------
// Kernel B (row kernel), REVERSE block order: block i handles row-chunk
// (1023 - i), walking x tail -> head so residual reads hit the L2 lines
// conv1 just left behind (L2 persists across launches; only L1 flushes).
//  phase 1: load h1 rows (L2), phase 2: conv2+bn+sign -> sh2,
//  phase 3: conv3+bn+prelu+residual+prelu, 4px x 32ch/thread, 128-bit I/O,
//           __stwt (no-allocate) writes so out doesn't evict x.
// ---------------------------------------------------------------------------
__global__ void __launch_bounds__(256) k_row(
    const float* __restrict__ x, float* __restrict__ out,
    const float* __restrict__ a3p, const float* __restrict__ aoutp)
{
    // sh2 16B-aligned: read via uint4 in phase 3 (R11 lesson).
    __shared__ __align__(16) uint32_t sh2[WW];
    __shared__ __align__(16) uint32_t sh1[3][WW + 2]; // col +1 shift; ends zero
    __shared__ uint32_t sw2[CI][9];
    __shared__ float sinv2[CI], sbb2[CI];
    __shared__ uint32_t sw3[CC];
    __shared__ float sinv3[CC], sbb3[CC];

    int tid = threadIdx.x;
    int rb  = (BB * HH - 1) - blockIdx.x;   // REVERSED: tail of x first
    int row = rb & (HH - 1);
    int b   = rb >> 7;

    if (tid < CC) { sw3[tid] = g_w3m[tid]; sinv3[tid] = g_inv3[tid]; sbb3[tid] = g_bb3[tid]; }
    if (tid < CI) {
        sinv2[tid] = g_inv2[tid]; sbb2[tid] = g_bb2[tid];
        #pragma unroll
        for (int t9 = 0; t9 < 9; t9++) sw2[tid][t9] = g_w2m[tid][t9];
    }

    // ---- Phase 1: h1 rows (from L2-resident g_h1b) ----
    const uint32_t* h1 = g_h1b + (size_t)b * HW;
    #pragma unroll
    for (int r = 0; r < 3; r++) {
        int y = row - 1 + r;
        sh1[r][tid + 1] = (y >= 0 && y < HH) ? h1[y * WW + tid] : 0u;
    }
    if (tid < 3) { sh1[tid][0] = 0u; sh1[tid][WW + 1] = 0u; }
    __syncthreads();

    // ---- Phase 2: conv2+bn+sign for pixel w = tid ----
    {
        uint32_t n[9];
        #pragma unroll
        for (int t = 0; t < 9; t++)
            n[t] = sh1[t / 3][tid + t % 3];   // col tid-1+(t%3), +1 shift

        uint32_t h2b = 0;
        const bool interior = (row > 0) & (row < HH - 1) & (tid > 0) & (tid < WW - 1);
        if (interior) {
            #pragma unroll
            for (int oc = 0; oc < CI; oc++) {
                int pc = 0;
                #pragma unroll
                for (int t = 0; t < 9; t++) pc += __popc(n[t] ^ sw2[oc][t]);
                float v = __fadd_rn(__fmul_rn((float)(288 - 2 * pc), sinv2[oc]), sbb2[oc]);
                if (v > 0.f) h2b |= (1u << oc);
            }
        } else {
            bool ok[9];
            #pragma unroll
            for (int t = 0; t < 9; t++) {
                int yy = row + t / 3 - 1, xx = tid + t % 3 - 1;
                ok[t] = (yy >= 0) & (yy < HH) & (xx >= 0) & (xx < WW);
            }
            #pragma unroll
            for (int oc = 0; oc < CI; oc++) {
                int z = 0;
                #pragma unroll
                for (int t = 0; t < 9; t++) {
                    int c9 = 32 - 2 * __popc(n[t] ^ sw2[oc][t]);
                    z += ok[t] ? c9 : 0;
                }
                float v = __fadd_rn(__fmul_rn((float)z, sinv2[oc]), sbb2[oc]);
                if (v > 0.f) h2b |= (1u << oc);
            }
        }
        sh2[tid] = h2b;
    }
    __syncthreads();

    // ---- Phase 3: conv3 + residual, 4 px x 32 ch per thread, float4 I/O ----
    int px0 = (tid >> 2) << 2;          // 4-aligned pixel group in row
    int cq  = (tid & 3) * 32;           // channel quarter

    uint4 h2v = *(const uint4*)&sh2[px0];
    uint32_t h2[4] = { h2v.x, h2v.y, h2v.z, h2v.w };

    float a3   = a3p[0];
    float aout = aoutp[0];
    size_t base = (size_t)b * (CC * HW) + (size_t)row * WW + px0;
    const float* xp = x + base;
    float* op = out + base;

    #pragma unroll 8
    for (int c = 0; c < 32; c++) {
        int ch = cq + c;
        uint32_t wc = sw3[ch];
        float inv = sinv3[ch], bb = sbb3[ch];
        float v0 = __fadd_rn(__fmul_rn((float)(32 - 2 * __popc(h2[0] ^ wc)), inv), bb);
        float v1 = __fadd_rn(__fmul_rn((float)(32 - 2 * __popc(h2[1] ^ wc)), inv), bb);
        float v2 = __fadd_rn(__fmul_rn((float)(32 - 2 * __popc(h2[2] ^ wc)), inv), bb);
        float v3 = __fadd_rn(__fmul_rn((float)(32 - 2 * __popc(h2[3] ^ wc)), inv), bb);
        v0 = (v0 >= 0.f) ? v0 : a3 * v0;
        v1 = (v1 >= 0.f) ? v1 : a3 * v1;
        v2 = (v2 >= 0.f) ? v2 : a3 * v2;
        v3 = (v3 >= 0.f) ? v3 : a3 * v3;
        float4 xv = *(const float4*)(xp + (size_t)ch * HW);
        float s0 = v0 + xv.x, s1 = v1 + xv.y, s2 = v2 + xv.z, s3 = v3 + xv.w;
        s0 = (s0 >= 0.f) ? s0 : aout * s0;
        s1 = (s1 >= 0.f) ? s1 : aout * s1;
        s2 = (s2 >= 0.f) ? s2 : aout * s2;
        s3 = (s3 >= 0.f) ? s3 : aout * s3;
        __stwt((float4*)(op + (size_t)ch * HW), make_float4(s0, s1, s2, s3));
    }
}

// ---------------------------------------------------------------------------
extern "C" void kernel_launch(void* const* d_in, const int* in_sizes, int n_in,
                              void* d_out, int out_size)
{
    const float* x  = (const float*)d_in[0];
    const float* w1 = (const float*)d_in[1];
    const float* g1 = (const float*)d_in[2];
    const float* b1 = (const float*)d_in[3];
    const float* m1 = (const float*)d_in[4];
    const float* v1 = (const float*)d_in[5];
    // d_in[6] = a1 (unused: prelu with a>0 never changes the following sign)
    const float* w2 = (const float*)d_in[7];
    const float* g2 = (const float*)d_in[8];
    const float* b2 = (const float*)d_in[9];
    const float* m2 = (const float*)d_in[10];
    const float* v2 = (const float*)d_in[11];
    // d_in[12] = a2 (unused, same reason)
    const float* w3 = (const float*)d_in[13];
    const float* g3 = (const float*)d_in[14];
    const float* b3 = (const float*)d_in[15];
    const float* m3 = (const float*)d_in[16];
    const float* v3 = (const float*)d_in[17];
    const float* a3 = (const float*)d_in[18];
    const float* ao = (const float*)d_in[19];
    float* out = (float*)d_out;

    prep_kernel<<<68, 256>>>(w1, g1, b1, m1, v1,
                             w2, g2, b2, m2, v2,
                             w3, g3, b3, m3, v3);

    k_conv1<<<(BB * HW) / 256, 256>>>(x);     // forward: leaves tail of x in L2

    k_row<<<BB * HH, 256>>>(x, out, a3, ao);  // reverse: consumes tail first
}